// round 15
// baseline (speedup 1.0000x reference)
#include <cuda_runtime.h>
#include <cuda_fp16.h>
#include <cstdint>
#include <math.h>

// ---------------- problem constants ----------------
#define BATCH  4096
#define NPED   64
#define HD     64
#define G2     64
#define KDIM   4096
#define NB     1024
#define BN_EPS 1e-5f

// ---------------- GEMM tiling (R9 config) ----------------
#define BM 128
#define BNv 256
#define BK 64                   // two 32-half panels per stage
#define NK2 (KDIM / BK)         // 64 iterations
#define STAGES 3
#define ROWB 80                 // padded panel row bytes (32 halves + 8 pad)
#define A_PANEL (128 * ROWB)    // 10240
#define B_PANEL (256 * ROWB)    // 20480
#define A_BYTES (2 * A_PANEL)   // 20480
#define B_BYTES (2 * B_PANEL)   // 40960
#define STAGE_BYTES (A_BYTES + B_BYTES)          // 61440
#define GEMM_SMEM (STAGES * STAGE_BYTES)         // 184320

// ---------------- device scratch ----------------
__device__ __half g_A [(size_t)BATCH * KDIM];   // pooled features, fp16
__device__ __half g_Bt[(size_t)NB * KDIM];      // W^T (K-major), fp16
__device__ float  g_sum[NB];
__device__ float  g_sumsq[NB];

// ---------------- helpers ----------------
__device__ __forceinline__ uint32_t h2u(__half2 h) {
    return *reinterpret_cast<uint32_t*>(&h);
}

__device__ __forceinline__ uint32_t smem_u32(const void* p) {
    uint32_t a;
    asm("{ .reg .u64 t; cvta.to.shared.u64 t, %1; cvt.u32.u64 %0, t; }"
        : "=r"(a) : "l"(p));
    return a;
}

__device__ __forceinline__ void cp16(uint32_t dst, const void* src) {
    asm volatile("cp.async.cg.shared.global [%0], [%1], 16;"
                 :: "r"(dst), "l"(src) : "memory");
}

#define CP_COMMIT() asm volatile("cp.async.commit_group;" ::: "memory")
#define CP_WAIT(n)  asm volatile("cp.async.wait_group %0;" :: "n"(n) : "memory")

#define LDM4(r0, r1, r2, r3, a)                                         \
    asm volatile("ldmatrix.sync.aligned.m8n8.x4.shared.b16 "            \
                 "{%0,%1,%2,%3}, [%4];"                                 \
                 : "=r"(r0), "=r"(r1), "=r"(r2), "=r"(r3) : "r"(a))

#define MMA16816(c, a, b)                                               \
    asm volatile("mma.sync.aligned.m16n8k16.row.col.f32.f16.f16.f32 "   \
                 "{%0,%1,%2,%3}, {%4,%5,%6,%7}, {%8,%9}, {%0,%1,%2,%3};"\
                 : "+f"((c)[0]), "+f"((c)[1]), "+f"((c)[2]), "+f"((c)[3])\
                 : "r"((a)[0]), "r"((a)[1]), "r"((a)[2]), "r"((a)[3]),  \
                   "r"((b)[0]), "r"((b)[1]))

// ---------------------------------------------------------------------------
// Kernel 1 (merged, 64 threads — R12 version): blocks [0,4096) social pooling
// -> fp16 A rows (uint4 stores) + zero BN stats; blocks [4096,5120) W -> Bt.
// ---------------------------------------------------------------------------
__global__ __launch_bounds__(64) void prep_kernel(
    const float* __restrict__ h,
    const float* __restrict__ pos,
    const float* __restrict__ W)
{
    __shared__ float buf[4224];          // pool: sp[4096]+spos[128f]; transp: 64x65
    const int blk = blockIdx.x;
    const int t   = threadIdx.x;

    if (blk < BATCH) {
        // ---------------- pooling path ----------------
        float* sp = buf;
        float2* spos = reinterpret_cast<float2*>(buf + 4096);
        const int base = (blk >> 6) << 6;

        if (blk < 16) {
            g_sum  [blk * 64 + t] = 0.0f;
            g_sumsq[blk * 64 + t] = 0.0f;
        }

        for (int k = t; k < 4096; k += 64) sp[k] = 0.0f;
        spos[t] = reinterpret_cast<const float2*>(pos)[base + t];
        __syncthreads();

        const int local_i = blk - base;
        const float2 pi = spos[local_i];
        const float tlx = pi.x - 1.0f, tly = pi.y + 1.0f;
        const float brx = pi.x + 1.0f, bry = pi.y - 1.0f;

        for (int j = 0; j < NPED; ++j) {
            if (j == local_i) continue;
            const float2 pj = spos[j];
            if (pj.x >= brx || pj.x <= tlx || pj.y >= tly || pj.y <= bry) continue;
            int cx = (int)floorf((pj.x - tlx) / 2.0f * 8.0f);
            int cy = (int)floorf((tly - pj.y) / 2.0f * 8.0f);
            int cell = min(max(cx + cy * 8, 0), G2 - 1);
            sp[cell * HD + t] += h[(size_t)(base + j) * HD + t];
        }
        __syncthreads();

        // vectorized fp16 output: 512 uint4 per row, 8 per thread
        uint4* dst = reinterpret_cast<uint4*>(g_A + (size_t)blk * KDIM);
#pragma unroll
        for (int i = 0; i < 8; ++i) {
            const int c = t + i * 64;            // uint4 index
            const float4 a = *reinterpret_cast<const float4*>(&sp[c * 8]);
            const float4 b = *reinterpret_cast<const float4*>(&sp[c * 8 + 4]);
            uint4 o;
            o.x = h2u(__floats2half2_rn(a.x, a.y));
            o.y = h2u(__floats2half2_rn(a.z, a.w));
            o.z = h2u(__floats2half2_rn(b.x, b.y));
            o.w = h2u(__floats2half2_rn(b.z, b.w));
            dst[c] = o;
        }
    } else {
        // ---------------- W transpose path ----------------
        const int idx = blk - BATCH;             // 0..1023
        const int k0  = (idx >> 4) * 64;         // 64 k-tiles
        const int n0  = (idx & 15) * 64;         // 16 n-tiles

#pragma unroll 8
        for (int kk = 0; kk < 64; ++kk)
            buf[kk * 65 + t] = W[(size_t)(k0 + kk) * NB + n0 + t];
        __syncthreads();

        uint4* dst = reinterpret_cast<uint4*>(g_Bt + (size_t)(n0 + t) * KDIM + k0);
#pragma unroll
        for (int c8 = 0; c8 < 8; ++c8) {
            const float* col = &buf[(c8 * 8) * 65 + t];
            uint4 o;
            o.x = h2u(__floats2half2_rn(col[0],      col[65]));
            o.y = h2u(__floats2half2_rn(col[2 * 65], col[3 * 65]));
            o.z = h2u(__floats2half2_rn(col[4 * 65], col[5 * 65]));
            o.w = h2u(__floats2half2_rn(col[6 * 65], col[7 * 65]));
            dst[c8] = o;
        }
    }
}

// ---------------------------------------------------------------------------
// Kernel 2: fp16 mma.sync GEMM (R9 config) + fused BN column stats.
// CTA 128x256, BK=64, 3-stage cp.async, one sync/iter. Warps 2(M) x 4(N),
// warp tile 64x64.
// ---------------------------------------------------------------------------
__global__ __launch_bounds__(256) void gemm_kernel(
    const __half* __restrict__ A,   // [BATCH, KDIM]
    const __half* __restrict__ Bt,  // [NB, KDIM]
    const float* __restrict__ bias,
    float* __restrict__ X)          // [BATCH, NB]
{
    extern __shared__ __align__(16) char dsm[];
    const uint32_t sbase = smem_u32(dsm);
    const int t    = threadIdx.x;
    const int warp = t >> 5, lane = t & 31;
    const int m0 = blockIdx.y * BM;
    const int n0 = blockIdx.x * BNv;
    const int warp_m = warp & 1;     // 64-row slab
    const int warp_n = warp >> 1;    // 64-col slab

    float acc[4][8][4];
#pragma unroll
    for (int i = 0; i < 4; ++i)
#pragma unroll
        for (int j = 0; j < 8; ++j)
#pragma unroll
            for (int e = 0; e < 4; ++e) acc[i][j][e] = 0.0f;

    auto load_stage = [&](int s, int kt) {
        const int kk = kt * BK;
        const uint32_t S  = sbase + (uint32_t)s * STAGE_BYTES;
        const uint32_t SB = S + A_BYTES;
#pragma unroll
        for (int i = 0; i < 4; ++i) {
            const int id = t + i * 256;
            const int r = id >> 3, c8 = id & 7;
            cp16(S + (c8 >> 2) * A_PANEL + r * ROWB + (c8 & 3) * 16,
                 A + (size_t)(m0 + r) * KDIM + kk + c8 * 8);
        }
#pragma unroll
        for (int i = 0; i < 8; ++i) {
            const int id = t + i * 256;
            const int r = id >> 3, c8 = id & 7;
            cp16(SB + (c8 >> 2) * B_PANEL + r * ROWB + (c8 & 3) * 16,
                 Bt + (size_t)(n0 + r) * KDIM + kk + c8 * 8);
        }
    };

    load_stage(0, 0); CP_COMMIT();
    load_stage(1, 1); CP_COMMIT();

    const int q  = lane >> 3;   // 0..3
    const int lr = lane & 7;

    int cur = 0;
    for (int kt = 0; kt < NK2; ++kt) {
        CP_WAIT(1);
        __syncthreads();

        if (kt + 2 < NK2) {
            load_stage((cur + 2) % STAGES, kt + 2);
        }
        CP_COMMIT();

        const uint32_t S  = sbase + (uint32_t)cur * STAGE_BYTES;
        const uint32_t SB = S + A_BYTES;

#pragma unroll
        for (int ks = 0; ks < 4; ++ks) {
            const uint32_t pA = S  + (ks >> 1) * A_PANEL;
            const uint32_t pB = SB + (ks >> 1) * B_PANEL;
            const int kc = (ks & 1) * 16;
            uint32_t aF[4][4];
            uint32_t bF[8][2];
#pragma unroll
            for (int mi = 0; mi < 4; ++mi) {
                const int row  = warp_m * 64 + mi * 16 + (q & 1) * 8 + lr;
                const int colh = kc + (q >> 1) * 8;
                LDM4(aF[mi][0], aF[mi][1], aF[mi][2], aF[mi][3],
                     pA + row * ROWB + colh * 2);
            }
#pragma unroll
            for (int pi = 0; pi < 4; ++pi) {
                const int row  = warp_n * 64 + pi * 16 + (q >> 1) * 8 + lr;
                const int colh = kc + (q & 1) * 8;
                uint32_t r0, r1, r2, r3;
                LDM4(r0, r1, r2, r3, pB + row * ROWB + colh * 2);
                bF[pi * 2 + 0][0] = r0;  bF[pi * 2 + 0][1] = r1;
                bF[pi * 2 + 1][0] = r2;  bF[pi * 2 + 1][1] = r3;
            }
#pragma unroll
            for (int mi = 0; mi < 4; ++mi)
#pragma unroll
                for (int ni = 0; ni < 8; ++ni)
                    MMA16816(acc[mi][ni], aF[mi], bF[ni]);
        }
        cur = (cur + 1) % STAGES;
    }

    // epilogue: bias add, store, fused column sum/sumsq
    const int er = lane >> 2;         // 0..7
    const int ec = (lane & 3) * 2;
#pragma unroll
    for (int ni = 0; ni < 8; ++ni) {
        const int n  = n0 + warp_n * 64 + ni * 8 + ec;
        const float b0 = bias[n], b1 = bias[n + 1];
        float s0 = 0.f, s1 = 0.f, q0 = 0.f, q1 = 0.f;
#pragma unroll
        for (int mi = 0; mi < 4; ++mi) {
            const int mrow = m0 + warp_m * 64 + mi * 16 + er;
            float v0 = acc[mi][ni][0] + b0;
            float v1 = acc[mi][ni][1] + b1;
            float v2 = acc[mi][ni][2] + b0;
            float v3 = acc[mi][ni][3] + b1;
            *reinterpret_cast<float2*>(&X[(size_t)mrow * NB + n]) =
                make_float2(v0, v1);
            *reinterpret_cast<float2*>(&X[(size_t)(mrow + 8) * NB + n]) =
                make_float2(v2, v3);
            s0 += v0 + v2;           s1 += v1 + v3;
            q0 += v0 * v0 + v2 * v2; q1 += v1 * v1 + v3 * v3;
        }
#pragma unroll
        for (int off = 4; off < 32; off <<= 1) {
            s0 += __shfl_xor_sync(0xFFFFFFFFu, s0, off);
            s1 += __shfl_xor_sync(0xFFFFFFFFu, s1, off);
            q0 += __shfl_xor_sync(0xFFFFFFFFu, q0, off);
            q1 += __shfl_xor_sync(0xFFFFFFFFu, q1, off);
        }
        if (er == 0) {
            atomicAdd(&g_sum[n],       s0);
            atomicAdd(&g_sum[n + 1],   s1);
            atomicAdd(&g_sumsq[n],     q0);
            atomicAdd(&g_sumsq[n + 1], q1);
        }
    }
}

// ---------------------------------------------------------------------------
// Kernel 3: batchnorm + ReLU, 2x float4 per thread, in place
// ---------------------------------------------------------------------------
__global__ __launch_bounds__(256) void apply_kernel(
    float* __restrict__ X,
    const float* __restrict__ gamma,
    const float* __restrict__ beta)
{
    const float inv_n = 1.0f / (float)BATCH;
#pragma unroll
    for (int u = 0; u < 2; ++u) {
        const int i4 = (blockIdx.x * 2 + u) * 256 + threadIdx.x;
        const int c4 = i4 & (NB / 4 - 1);
        float4 s  = reinterpret_cast<const float4*>(g_sum)[c4];
        float4 ss = reinterpret_cast<const float4*>(g_sumsq)[c4];
        float4 g  = reinterpret_cast<const float4*>(gamma)[c4];
        float4 be = reinterpret_cast<const float4*>(beta)[c4];
        float4 v  = reinterpret_cast<float4*>(X)[i4];

        float m, is;
        m = s.x * inv_n; is = rsqrtf(ss.x * inv_n - m * m + BN_EPS);
        v.x = fmaxf((v.x - m) * is * g.x + be.x, 0.0f);
        m = s.y * inv_n; is = rsqrtf(ss.y * inv_n - m * m + BN_EPS);
        v.y = fmaxf((v.y - m) * is * g.y + be.y, 0.0f);
        m = s.z * inv_n; is = rsqrtf(ss.z * inv_n - m * m + BN_EPS);
        v.z = fmaxf((v.z - m) * is * g.z + be.z, 0.0f);
        m = s.w * inv_n; is = rsqrtf(ss.w * inv_n - m * m + BN_EPS);
        v.w = fmaxf((v.w - m) * is * g.w + be.w, 0.0f);

        reinterpret_cast<float4*>(X)[i4] = v;
    }
}

// ---------------------------------------------------------------------------
// launch
// ---------------------------------------------------------------------------
extern "C" void kernel_launch(void* const* d_in, const int* in_sizes, int n_in,
                              void* d_out, int out_size)
{
    const float* h_states = (const float*)d_in[0];
    const float* end_pos  = (const float*)d_in[2];
    const float* W        = (const float*)d_in[4];
    const float* b        = (const float*)d_in[5];
    const float* gamma    = (const float*)d_in[6];
    const float* beta     = (const float*)d_in[7];
    float* X = (float*)d_out;

    __half *Ap, *Btp;
    cudaGetSymbolAddress((void**)&Ap,  g_A);
    cudaGetSymbolAddress((void**)&Btp, g_Bt);

    cudaFuncSetAttribute(gemm_kernel,
                         cudaFuncAttributeMaxDynamicSharedMemorySize, GEMM_SMEM);

    prep_kernel<<<BATCH + 1024, 64>>>(h_states, end_pos, W);

    gemm_kernel<<<dim3(NB / BNv, BATCH / BM), 256, GEMM_SMEM>>>(Ap, Btp, b, X);

    apply_kernel<<<(BATCH * NB / 8) / 256, 256>>>(X, gamma, beta);
}

// round 16
// speedup vs baseline: 1.0549x; 1.0549x over previous
#include <cuda_runtime.h>
#include <cuda_fp16.h>
#include <cstdint>
#include <math.h>

// ---------------- problem constants ----------------
#define BATCH  4096
#define NPED   64
#define HD     64
#define G2     64
#define KDIM   4096
#define NB     1024
#define BN_EPS 1e-5f

// ---------------- GEMM tiling (R12 config: best measured) ----------------
#define BM 128
#define BNv 128
#define BK 32
#define NK (KDIM / BK)          // 128
#define STAGES 4
#define ROWB 80                 // padded row bytes (32 halves + 8 pad)
#define STAGE_BYTES (2 * 128 * ROWB)     // 20480
#define GEMM_SMEM (STAGES * STAGE_BYTES) // 81920 -> 2 CTAs/SM
#define NCTA 256                // (NB/BNv) * (BATCH/BM) = 8*32

// ---------------- device scratch ----------------
__device__ __half g_A [(size_t)BATCH * KDIM];   // pooled features, fp16
__device__ __half g_Bt[(size_t)NB * KDIM];      // W^T (K-major), fp16
__device__ float  g_sum[NB];
__device__ float  g_sumsq[NB];
__device__ unsigned g_bar;                       // grid barrier counter

// ---------------- helpers ----------------
__device__ __forceinline__ uint32_t h2u(__half2 h) {
    return *reinterpret_cast<uint32_t*>(&h);
}

__device__ __forceinline__ uint32_t smem_u32(const void* p) {
    uint32_t a;
    asm("{ .reg .u64 t; cvta.to.shared.u64 t, %1; cvt.u32.u64 %0, t; }"
        : "=r"(a) : "l"(p));
    return a;
}

__device__ __forceinline__ void cp16(uint32_t dst, const void* src) {
    asm volatile("cp.async.cg.shared.global [%0], [%1], 16;"
                 :: "r"(dst), "l"(src) : "memory");
}

#define CP_COMMIT() asm volatile("cp.async.commit_group;" ::: "memory")
#define CP_WAIT(n)  asm volatile("cp.async.wait_group %0;" :: "n"(n) : "memory")

#define LDM4(r0, r1, r2, r3, a)                                         \
    asm volatile("ldmatrix.sync.aligned.m8n8.x4.shared.b16 "            \
                 "{%0,%1,%2,%3}, [%4];"                                 \
                 : "=r"(r0), "=r"(r1), "=r"(r2), "=r"(r3) : "r"(a))

#define MMA16816(c, a, b)                                               \
    asm volatile("mma.sync.aligned.m16n8k16.row.col.f32.f16.f16.f32 "   \
                 "{%0,%1,%2,%3}, {%4,%5,%6,%7}, {%8,%9}, {%0,%1,%2,%3};"\
                 : "+f"((c)[0]), "+f"((c)[1]), "+f"((c)[2]), "+f"((c)[3])\
                 : "r"((a)[0]), "r"((a)[1]), "r"((a)[2]), "r"((a)[3]),  \
                   "r"((b)[0]), "r"((b)[1]))

// ---------------------------------------------------------------------------
// Kernel 1 (merged, 64 threads): blocks [0,4096) social pooling with
// neighbor-list compaction -> fp16 A rows; blocks [4096,5120) W -> Bt.
// Also zeroes BN stats + barrier counter.
// ---------------------------------------------------------------------------
__global__ __launch_bounds__(64) void prep_kernel(
    const float* __restrict__ h,
    const float* __restrict__ pos,
    const float* __restrict__ W)
{
    __shared__ float buf[4224];          // pool: sp[4096]+spos; transp: 64x65
    __shared__ int    s_cnt;
    __shared__ uint16_t s_ent[64];       // packed (cell<<8)|j
    const int blk = blockIdx.x;
    const int t   = threadIdx.x;

    if (blk < BATCH) {
        // ---------------- pooling path ----------------
        float* sp = buf;
        float2* spos = reinterpret_cast<float2*>(buf + 4096);
        const int base = (blk >> 6) << 6;

        if (blk < 16) {
            g_sum  [blk * 64 + t] = 0.0f;
            g_sumsq[blk * 64 + t] = 0.0f;
        }
        if (blk == 0 && t == 0) g_bar = 0;

        for (int k = t; k < 4096; k += 64) sp[k] = 0.0f;
        spos[t] = reinterpret_cast<const float2*>(pos)[base + t];
        if (t == 0) s_cnt = 0;
        __syncthreads();

        const int local_i = blk - base;
        const float2 pi = spos[local_i];
        const float tlx = pi.x - 1.0f, tly = pi.y + 1.0f;
        const float brx = pi.x + 1.0f, bry = pi.y - 1.0f;

        // compaction: thread t evaluates ped j = t once
        if (t != local_i) {
            const float2 pj = spos[t];
            if (!(pj.x >= brx || pj.x <= tlx || pj.y >= tly || pj.y <= bry)) {
                int cx = (int)floorf((pj.x - tlx) / 2.0f * 8.0f);
                int cy = (int)floorf((tly - pj.y) / 2.0f * 8.0f);
                int cell = min(max(cx + cy * 8, 0), G2 - 1);
                int slot = atomicAdd(&s_cnt, 1);
                s_ent[slot] = (uint16_t)((cell << 8) | t);
            }
        }
        __syncthreads();

        const int cnt = s_cnt;
        for (int e = 0; e < cnt; ++e) {
            const int ent  = s_ent[e];
            const int cell = ent >> 8;
            const int j    = ent & 255;
            sp[cell * HD + t] += h[(size_t)(base + j) * HD + t];
        }
        __syncthreads();

        // vectorized fp16 output: 512 uint4 per row, 8 per thread
        uint4* dst = reinterpret_cast<uint4*>(g_A + (size_t)blk * KDIM);
#pragma unroll
        for (int i = 0; i < 8; ++i) {
            const int c = t + i * 64;            // uint4 index
            const float4 a = *reinterpret_cast<const float4*>(&sp[c * 8]);
            const float4 b = *reinterpret_cast<const float4*>(&sp[c * 8 + 4]);
            uint4 o;
            o.x = h2u(__floats2half2_rn(a.x, a.y));
            o.y = h2u(__floats2half2_rn(a.z, a.w));
            o.z = h2u(__floats2half2_rn(b.x, b.y));
            o.w = h2u(__floats2half2_rn(b.z, b.w));
            dst[c] = o;
        }
    } else {
        // ---------------- W transpose path ----------------
        const int idx = blk - BATCH;             // 0..1023
        const int k0  = (idx >> 4) * 64;         // 64 k-tiles
        const int n0  = (idx & 15) * 64;         // 16 n-tiles

#pragma unroll 8
        for (int kk = 0; kk < 64; ++kk)
            buf[kk * 65 + t] = W[(size_t)(k0 + kk) * NB + n0 + t];
        __syncthreads();

        uint4* dst = reinterpret_cast<uint4*>(g_Bt + (size_t)(n0 + t) * KDIM + k0);
#pragma unroll
        for (int c8 = 0; c8 < 8; ++c8) {
            const float* col = &buf[(c8 * 8) * 65 + t];
            uint4 o;
            o.x = h2u(__floats2half2_rn(col[0],      col[65]));
            o.y = h2u(__floats2half2_rn(col[2 * 65], col[3 * 65]));
            o.z = h2u(__floats2half2_rn(col[4 * 65], col[5 * 65]));
            o.w = h2u(__floats2half2_rn(col[6 * 65], col[7 * 65]));
            dst[c8] = o;
        }
    }
}

// ---------------------------------------------------------------------------
// Kernel 2: fp16 mma.sync GEMM + FULLY FUSED batchnorm + ReLU.
// CTA 128x128, BK=32, 4-stage cp.async, 2 CTAs/SM -> all 256 CTAs resident.
// Epilogue: bias+stats -> grid barrier -> normalize in-register -> store once.
// ---------------------------------------------------------------------------
__global__ __launch_bounds__(256, 2) void gemm_kernel(
    const __half* __restrict__ A,   // [BATCH, KDIM]
    const __half* __restrict__ Bt,  // [NB, KDIM]
    const float* __restrict__ bias,
    const float* __restrict__ gamma,
    const float* __restrict__ beta,
    float* __restrict__ X)          // [BATCH, NB]
{
    extern __shared__ __align__(16) char dsm[];
    const uint32_t sbase = smem_u32(dsm);
    const int t    = threadIdx.x;
    const int warp = t >> 5, lane = t & 31;
    const int m0 = blockIdx.y * BM;
    const int n0 = blockIdx.x * BNv;
    const int warp_m = warp & 1;     // 64-row slab
    const int warp_n = warp >> 1;    // 32-col slab

    float acc[4][4][4];
#pragma unroll
    for (int i = 0; i < 4; ++i)
#pragma unroll
        for (int j = 0; j < 4; ++j)
#pragma unroll
            for (int e = 0; e < 4; ++e) acc[i][j][e] = 0.0f;

    auto load_stage = [&](int s, int kt) {
        const int kk = kt * BK;
        const uint32_t sA = sbase + (uint32_t)s * STAGE_BYTES;
        const uint32_t sB = sA + 128 * ROWB;
#pragma unroll
        for (int i = 0; i < 2; ++i) {
            const int id = t + i * 256;
            const int r = id >> 2, c = (id & 3) * 8;
            cp16(sA + r * ROWB + c * 2, A  + (size_t)(m0 + r) * KDIM + kk + c);
            cp16(sB + r * ROWB + c * 2, Bt + (size_t)(n0 + r) * KDIM + kk + c);
        }
    };

#pragma unroll
    for (int s = 0; s < STAGES - 1; ++s) {
        load_stage(s, s);
        CP_COMMIT();
    }

    const int q  = lane >> 3;   // 0..3
    const int lr = lane & 7;

    for (int kt = 0; kt < NK; ++kt) {
        CP_WAIT(2);
        __syncthreads();

        if (kt + STAGES - 1 < NK)
            load_stage((kt + STAGES - 1) % STAGES, kt + STAGES - 1);
        CP_COMMIT();

        const uint32_t sA = sbase + (uint32_t)(kt % STAGES) * STAGE_BYTES;
        const uint32_t sB = sA + 128 * ROWB;

#pragma unroll
        for (int ks = 0; ks < 2; ++ks) {
            uint32_t aF[4][4];
            uint32_t bF[4][2];
#pragma unroll
            for (int mi = 0; mi < 4; ++mi) {
                const int row  = warp_m * 64 + mi * 16 + (q & 1) * 8 + lr;
                const int colh = ks * 16 + (q >> 1) * 8;
                LDM4(aF[mi][0], aF[mi][1], aF[mi][2], aF[mi][3],
                     sA + row * ROWB + colh * 2);
            }
#pragma unroll
            for (int pi = 0; pi < 2; ++pi) {
                const int row  = warp_n * 32 + pi * 16 + (q >> 1) * 8 + lr;
                const int colh = ks * 16 + (q & 1) * 8;
                uint32_t r0, r1, r2, r3;
                LDM4(r0, r1, r2, r3, sB + row * ROWB + colh * 2);
                bF[pi * 2 + 0][0] = r0;  bF[pi * 2 + 0][1] = r1;
                bF[pi * 2 + 1][0] = r2;  bF[pi * 2 + 1][1] = r3;
            }
#pragma unroll
            for (int mi = 0; mi < 4; ++mi)
#pragma unroll
                for (int ni = 0; ni < 4; ++ni)
                    MMA16816(acc[mi][ni], aF[mi], bF[ni]);
        }
    }

    // ---- epilogue pass 1: bias add (in-register) + column stats ----
    const int er = lane >> 2;         // 0..7
    const int ec = (lane & 3) * 2;
#pragma unroll
    for (int ni = 0; ni < 4; ++ni) {
        const int n  = n0 + warp_n * 32 + ni * 8 + ec;
        const float b0 = bias[n], b1 = bias[n + 1];
        float s0 = 0.f, s1 = 0.f, q0 = 0.f, q1 = 0.f;
#pragma unroll
        for (int mi = 0; mi < 4; ++mi) {
            float v0 = acc[mi][ni][0] + b0;
            float v1 = acc[mi][ni][1] + b1;
            float v2 = acc[mi][ni][2] + b0;
            float v3 = acc[mi][ni][3] + b1;
            acc[mi][ni][0] = v0; acc[mi][ni][1] = v1;
            acc[mi][ni][2] = v2; acc[mi][ni][3] = v3;
            s0 += v0 + v2;           s1 += v1 + v3;
            q0 += v0 * v0 + v2 * v2; q1 += v1 * v1 + v3 * v3;
        }
#pragma unroll
        for (int off = 4; off < 32; off <<= 1) {
            s0 += __shfl_xor_sync(0xFFFFFFFFu, s0, off);
            s1 += __shfl_xor_sync(0xFFFFFFFFu, s1, off);
            q0 += __shfl_xor_sync(0xFFFFFFFFu, q0, off);
            q1 += __shfl_xor_sync(0xFFFFFFFFu, q1, off);
        }
        if (er == 0) {
            atomicAdd(&g_sum[n],       s0);
            atomicAdd(&g_sum[n + 1],   s1);
            atomicAdd(&g_sumsq[n],     q0);
            atomicAdd(&g_sumsq[n + 1], q1);
        }
    }

    // ---- grid-wide barrier (all 256 CTAs resident by construction) ----
    __threadfence();
    __syncthreads();
    if (t == 0) {
        atomicAdd(&g_bar, 1u);
        volatile unsigned* vb = &g_bar;
        while (*vb < NCTA) { }
    }
    __syncthreads();
    __threadfence();

    // ---- epilogue pass 2: normalize + ReLU + single store ----
    const float inv_n = 1.0f / (float)BATCH;
#pragma unroll
    for (int ni = 0; ni < 4; ++ni) {
        const int n  = n0 + warp_n * 32 + ni * 8 + ec;
        const float su0 = __ldcg(&g_sum[n]),     su1 = __ldcg(&g_sum[n + 1]);
        const float sq0 = __ldcg(&g_sumsq[n]),   sq1 = __ldcg(&g_sumsq[n + 1]);
        const float m0f = su0 * inv_n,           m1f = su1 * inv_n;
        const float is0 = rsqrtf(sq0 * inv_n - m0f * m0f + BN_EPS);
        const float is1 = rsqrtf(sq1 * inv_n - m1f * m1f + BN_EPS);
        const float sc0 = is0 * gamma[n],        sc1 = is1 * gamma[n + 1];
        const float of0 = beta[n] - m0f * sc0,   of1 = beta[n + 1] - m1f * sc1;
#pragma unroll
        for (int mi = 0; mi < 4; ++mi) {
            const int mrow = m0 + warp_m * 64 + mi * 16 + er;
            float2 o0, o1;
            o0.x = fmaxf(fmaf(acc[mi][ni][0], sc0, of0), 0.0f);
            o0.y = fmaxf(fmaf(acc[mi][ni][1], sc1, of1), 0.0f);
            o1.x = fmaxf(fmaf(acc[mi][ni][2], sc0, of0), 0.0f);
            o1.y = fmaxf(fmaf(acc[mi][ni][3], sc1, of1), 0.0f);
            *reinterpret_cast<float2*>(&X[(size_t)mrow * NB + n])       = o0;
            *reinterpret_cast<float2*>(&X[(size_t)(mrow + 8) * NB + n]) = o1;
        }
    }
}

// ---------------------------------------------------------------------------
// launch
// ---------------------------------------------------------------------------
extern "C" void kernel_launch(void* const* d_in, const int* in_sizes, int n_in,
                              void* d_out, int out_size)
{
    const float* h_states = (const float*)d_in[0];
    const float* end_pos  = (const float*)d_in[2];
    const float* W        = (const float*)d_in[4];
    const float* b        = (const float*)d_in[5];
    const float* gamma    = (const float*)d_in[6];
    const float* beta     = (const float*)d_in[7];
    float* X = (float*)d_out;

    __half *Ap, *Btp;
    cudaGetSymbolAddress((void**)&Ap,  g_A);
    cudaGetSymbolAddress((void**)&Btp, g_Bt);

    cudaFuncSetAttribute(gemm_kernel,
                         cudaFuncAttributeMaxDynamicSharedMemorySize, GEMM_SMEM);

    prep_kernel<<<BATCH + 1024, 64>>>(h_states, end_pos, W);

    gemm_kernel<<<dim3(NB / BNv, BATCH / BM), 256, GEMM_SMEM>>>(
        Ap, Btp, b, gamma, beta, X);
}

// round 17
// speedup vs baseline: 1.1559x; 1.0957x over previous
#include <cuda_runtime.h>
#include <cuda_fp16.h>
#include <cstdint>
#include <math.h>

// ---------------- problem constants ----------------
#define BATCH  4096
#define NPED   64
#define HD     64
#define G2     64
#define KDIM   4096
#define NB     1024
#define BN_EPS 1e-5f

// ---------------- GEMM tiling ----------------
#define BM 128
#define BNv 128
#define BK 32
#define NK (KDIM / BK)          // 128
#define STAGES 4
#define ROWB 80                 // padded row bytes (32 halves + 8 pad)
#define STAGE_BYTES (2 * 128 * ROWB)     // 20480
#define GEMM_SMEM (STAGES * STAGE_BYTES) // 81920 -> 2 CTAs/SM
#define NCTA 256

// ---------------- device scratch ----------------
__device__ __half g_A [(size_t)BATCH * KDIM];
__device__ __half g_Bt[(size_t)NB * KDIM];
__device__ float  g_sum[NB];
__device__ float  g_sumsq[NB];
__device__ unsigned g_bar;

// ---------------- helpers ----------------
__device__ __forceinline__ uint32_t h2u(__half2 h) {
    return *reinterpret_cast<uint32_t*>(&h);
}

__device__ __forceinline__ uint32_t smem_u32(const void* p) {
    uint32_t a;
    asm("{ .reg .u64 t; cvta.to.shared.u64 t, %1; cvt.u32.u64 %0, t; }"
        : "=r"(a) : "l"(p));
    return a;
}

__device__ __forceinline__ void cp16(uint32_t dst, const void* src) {
    asm volatile("cp.async.cg.shared.global [%0], [%1], 16;"
                 :: "r"(dst), "l"(src) : "memory");
}

#define CP_COMMIT() asm volatile("cp.async.commit_group;" ::: "memory")
#define CP_WAIT(n)  asm volatile("cp.async.wait_group %0;" :: "n"(n) : "memory")

#define LDM4(r0, r1, r2, r3, a)                                         \
    asm volatile("ldmatrix.sync.aligned.m8n8.x4.shared.b16 "            \
                 "{%0,%1,%2,%3}, [%4];"                                 \
                 : "=r"(r0), "=r"(r1), "=r"(r2), "=r"(r3) : "r"(a))

#define MMA16816(c, a, b)                                               \
    asm volatile("mma.sync.aligned.m16n8k16.row.col.f32.f16.f16.f32 "   \
                 "{%0,%1,%2,%3}, {%4,%5,%6,%7}, {%8,%9}, {%0,%1,%2,%3};"\
                 : "+f"((c)[0]), "+f"((c)[1]), "+f"((c)[2]), "+f"((c)[3])\
                 : "r"((a)[0]), "r"((a)[1]), "r"((a)[2]), "r"((a)[3]),  \
                   "r"((b)[0]), "r"((b)[1]))

// ---------------------------------------------------------------------------
// Kernel 1 (merged, 64 threads): pooling w/ neighbor compaction + W transpose
// ---------------------------------------------------------------------------
__global__ __launch_bounds__(64) void prep_kernel(
    const float* __restrict__ h,
    const float* __restrict__ pos,
    const float* __restrict__ W)
{
    __shared__ float buf[4224];
    __shared__ int    s_cnt;
    __shared__ uint16_t s_ent[64];
    const int blk = blockIdx.x;
    const int t   = threadIdx.x;

    if (blk < BATCH) {
        float* sp = buf;
        float2* spos = reinterpret_cast<float2*>(buf + 4096);
        const int base = (blk >> 6) << 6;

        if (blk < 16) {
            g_sum  [blk * 64 + t] = 0.0f;
            g_sumsq[blk * 64 + t] = 0.0f;
        }
        if (blk == 0 && t == 0) g_bar = 0;

        for (int k = t; k < 4096; k += 64) sp[k] = 0.0f;
        spos[t] = reinterpret_cast<const float2*>(pos)[base + t];
        if (t == 0) s_cnt = 0;
        __syncthreads();

        const int local_i = blk - base;
        const float2 pi = spos[local_i];
        const float tlx = pi.x - 1.0f, tly = pi.y + 1.0f;
        const float brx = pi.x + 1.0f, bry = pi.y - 1.0f;

        if (t != local_i) {
            const float2 pj = spos[t];
            if (!(pj.x >= brx || pj.x <= tlx || pj.y >= tly || pj.y <= bry)) {
                int cx = (int)floorf((pj.x - tlx) / 2.0f * 8.0f);
                int cy = (int)floorf((tly - pj.y) / 2.0f * 8.0f);
                int cell = min(max(cx + cy * 8, 0), G2 - 1);
                int slot = atomicAdd(&s_cnt, 1);
                s_ent[slot] = (uint16_t)((cell << 8) | t);
            }
        }
        __syncthreads();

        const int cnt = s_cnt;
        for (int e = 0; e < cnt; ++e) {
            const int ent  = s_ent[e];
            const int cell = ent >> 8;
            const int j    = ent & 255;
            sp[cell * HD + t] += h[(size_t)(base + j) * HD + t];
        }
        __syncthreads();

        uint4* dst = reinterpret_cast<uint4*>(g_A + (size_t)blk * KDIM);
#pragma unroll
        for (int i = 0; i < 8; ++i) {
            const int c = t + i * 64;
            const float4 a = *reinterpret_cast<const float4*>(&sp[c * 8]);
            const float4 b = *reinterpret_cast<const float4*>(&sp[c * 8 + 4]);
            uint4 o;
            o.x = h2u(__floats2half2_rn(a.x, a.y));
            o.y = h2u(__floats2half2_rn(a.z, a.w));
            o.z = h2u(__floats2half2_rn(b.x, b.y));
            o.w = h2u(__floats2half2_rn(b.z, b.w));
            dst[c] = o;
        }
    } else {
        const int idx = blk - BATCH;
        const int k0  = (idx >> 4) * 64;
        const int n0  = (idx & 15) * 64;

#pragma unroll 8
        for (int kk = 0; kk < 64; ++kk)
            buf[kk * 65 + t] = W[(size_t)(k0 + kk) * NB + n0 + t];
        __syncthreads();

        uint4* dst = reinterpret_cast<uint4*>(g_Bt + (size_t)(n0 + t) * KDIM + k0);
#pragma unroll
        for (int c8 = 0; c8 < 8; ++c8) {
            const float* col = &buf[(c8 * 8) * 65 + t];
            uint4 o;
            o.x = h2u(__floats2half2_rn(col[0],      col[65]));
            o.y = h2u(__floats2half2_rn(col[2 * 65], col[3 * 65]));
            o.z = h2u(__floats2half2_rn(col[4 * 65], col[5 * 65]));
            o.w = h2u(__floats2half2_rn(col[6 * 65], col[7 * 65]));
            dst[c8] = o;
        }
    }
}

// ---------------------------------------------------------------------------
// Kernel 2: fp16 mma.sync GEMM + fused BN + ReLU, fragment-double-buffered.
// ---------------------------------------------------------------------------
__global__ __launch_bounds__(256, 2) void gemm_kernel(
    const __half* __restrict__ A,
    const __half* __restrict__ Bt,
    const float* __restrict__ bias,
    const float* __restrict__ gamma,
    const float* __restrict__ beta,
    float* __restrict__ X)
{
    extern __shared__ __align__(16) char dsm[];
    const uint32_t sbase = smem_u32(dsm);
    const int t    = threadIdx.x;
    const int warp = t >> 5, lane = t & 31;
    const int m0 = blockIdx.y * BM;
    const int n0 = blockIdx.x * BNv;
    const int warp_m = warp & 1;
    const int warp_n = warp >> 1;

    float acc[4][4][4];
#pragma unroll
    for (int i = 0; i < 4; ++i)
#pragma unroll
        for (int j = 0; j < 4; ++j)
#pragma unroll
            for (int e = 0; e < 4; ++e) acc[i][j][e] = 0.0f;

    auto load_stage = [&](int s, int kt) {
        const int kk = kt * BK;
        const uint32_t sA = sbase + (uint32_t)s * STAGE_BYTES;
        const uint32_t sB = sA + 128 * ROWB;
#pragma unroll
        for (int i = 0; i < 2; ++i) {
            const int id = t + i * 256;
            const int r = id >> 2, c = (id & 3) * 8;
            cp16(sA + r * ROWB + c * 2, A  + (size_t)(m0 + r) * KDIM + kk + c);
            cp16(sB + r * ROWB + c * 2, Bt + (size_t)(n0 + r) * KDIM + kk + c);
        }
    };

#pragma unroll
    for (int s = 0; s < STAGES - 1; ++s) {
        load_stage(s, s);
        CP_COMMIT();
    }

    const int q  = lane >> 3;
    const int lr = lane & 7;
    // per-warp ldmatrix base offsets (row*ROWB precomputed pieces)
    const int aRowOff = (warp_m * 64 + (q & 1) * 8 + lr) * ROWB;
    const int aColOff = (q >> 1) * 16;            // bytes for 8 halves
    const int bRowOff = (warp_n * 32 + (q >> 1) * 8 + lr) * ROWB;
    const int bColOff = (q & 1) * 16;

    uint32_t aF[2][4][4];
    uint32_t bF[2][4][2];

    // fragment loader: stage address, ks (0/1), buffer
    auto ldfrag = [&](uint32_t sS, int ks, int pb) {
        const uint32_t sA = sS;
        const uint32_t sB = sS + 128 * ROWB;
        const int kcA = ks * 32 + aColOff;        // bytes
        const int kcB = ks * 32 + bColOff;
#pragma unroll
        for (int mi = 0; mi < 4; ++mi)
            LDM4(aF[pb][mi][0], aF[pb][mi][1], aF[pb][mi][2], aF[pb][mi][3],
                 sA + aRowOff + mi * (16 * ROWB) + kcA);
#pragma unroll
        for (int pi = 0; pi < 2; ++pi) {
            uint32_t r0, r1, r2, r3;
            LDM4(r0, r1, r2, r3, sB + bRowOff + pi * (16 * ROWB) + kcB);
            bF[pb][pi * 2 + 0][0] = r0;  bF[pb][pi * 2 + 0][1] = r1;
            bF[pb][pi * 2 + 1][0] = r2;  bF[pb][pi * 2 + 1][1] = r3;
        }
    };

    auto mma_block = [&](int pb) {
#pragma unroll
        for (int mi = 0; mi < 4; ++mi)
#pragma unroll
            for (int ni = 0; ni < 4; ++ni)
                MMA16816(acc[mi][ni], aF[pb][mi], bF[pb][ni]);
    };

    // prologue: stage 0 resident, load frag(kt=0, ks=0)
    CP_WAIT(2);
    __syncthreads();
    ldfrag(sbase, 0, 0);

    for (int kt = 0; kt < NK; ++kt) {
        const uint32_t sCur = sbase + (uint32_t)(kt % STAGES) * STAGE_BYTES;

        ldfrag(sCur, 1, 1);                       // prefetch ks=1

        if (kt + STAGES - 1 < NK)
            load_stage((kt + STAGES - 1) % STAGES, kt + STAGES - 1);
        CP_COMMIT();

        mma_block(0);                             // compute ks=0

        CP_WAIT(2);                               // stage kt+1 resident
        __syncthreads();                          // reads of stage kt-1 done

        if (kt + 1 < NK) {
            const uint32_t sNext =
                sbase + (uint32_t)((kt + 1) % STAGES) * STAGE_BYTES;
            ldfrag(sNext, 0, 0);                  // prefetch next kt, ks=0
        }

        mma_block(1);                             // compute ks=1
    }

    // ---- epilogue pass 1: bias add (in-register) + column stats ----
    const int er = lane >> 2;
    const int ec = (lane & 3) * 2;
#pragma unroll
    for (int ni = 0; ni < 4; ++ni) {
        const int n  = n0 + warp_n * 32 + ni * 8 + ec;
        const float b0 = bias[n], b1 = bias[n + 1];
        float s0 = 0.f, s1 = 0.f, q0 = 0.f, q1 = 0.f;
#pragma unroll
        for (int mi = 0; mi < 4; ++mi) {
            float v0 = acc[mi][ni][0] + b0;
            float v1 = acc[mi][ni][1] + b1;
            float v2 = acc[mi][ni][2] + b0;
            float v3 = acc[mi][ni][3] + b1;
            acc[mi][ni][0] = v0; acc[mi][ni][1] = v1;
            acc[mi][ni][2] = v2; acc[mi][ni][3] = v3;
            s0 += v0 + v2;           s1 += v1 + v3;
            q0 += v0 * v0 + v2 * v2; q1 += v1 * v1 + v3 * v3;
        }
#pragma unroll
        for (int off = 4; off < 32; off <<= 1) {
            s0 += __shfl_xor_sync(0xFFFFFFFFu, s0, off);
            s1 += __shfl_xor_sync(0xFFFFFFFFu, s1, off);
            q0 += __shfl_xor_sync(0xFFFFFFFFu, q0, off);
            q1 += __shfl_xor_sync(0xFFFFFFFFu, q1, off);
        }
        if (er == 0) {
            atomicAdd(&g_sum[n],       s0);
            atomicAdd(&g_sum[n + 1],   s1);
            atomicAdd(&g_sumsq[n],     q0);
            atomicAdd(&g_sumsq[n + 1], q1);
        }
    }

    // ---- grid-wide barrier (all 256 CTAs resident by construction) ----
    __threadfence();
    __syncthreads();
    if (t == 0) {
        atomicAdd(&g_bar, 1u);
        volatile unsigned* vb = &g_bar;
        while (*vb < NCTA) { }
    }
    __syncthreads();
    __threadfence();

    // ---- epilogue pass 2: normalize + ReLU + single store ----
    const float inv_n = 1.0f / (float)BATCH;
#pragma unroll
    for (int ni = 0; ni < 4; ++ni) {
        const int n  = n0 + warp_n * 32 + ni * 8 + ec;
        const float su0 = __ldcg(&g_sum[n]),     su1 = __ldcg(&g_sum[n + 1]);
        const float sq0 = __ldcg(&g_sumsq[n]),   sq1 = __ldcg(&g_sumsq[n + 1]);
        const float m0f = su0 * inv_n,           m1f = su1 * inv_n;
        const float is0 = rsqrtf(sq0 * inv_n - m0f * m0f + BN_EPS);
        const float is1 = rsqrtf(sq1 * inv_n - m1f * m1f + BN_EPS);
        const float sc0 = is0 * gamma[n],        sc1 = is1 * gamma[n + 1];
        const float of0 = beta[n] - m0f * sc0,   of1 = beta[n + 1] - m1f * sc1;
#pragma unroll
        for (int mi = 0; mi < 4; ++mi) {
            const int mrow = m0 + warp_m * 64 + mi * 16 + er;
            float2 o0, o1;
            o0.x = fmaxf(fmaf(acc[mi][ni][0], sc0, of0), 0.0f);
            o0.y = fmaxf(fmaf(acc[mi][ni][1], sc1, of1), 0.0f);
            o1.x = fmaxf(fmaf(acc[mi][ni][2], sc0, of0), 0.0f);
            o1.y = fmaxf(fmaf(acc[mi][ni][3], sc1, of1), 0.0f);
            *reinterpret_cast<float2*>(&X[(size_t)mrow * NB + n])       = o0;
            *reinterpret_cast<float2*>(&X[(size_t)(mrow + 8) * NB + n]) = o1;
        }
    }
}

// ---------------------------------------------------------------------------
// launch
// ---------------------------------------------------------------------------
extern "C" void kernel_launch(void* const* d_in, const int* in_sizes, int n_in,
                              void* d_out, int out_size)
{
    const float* h_states = (const float*)d_in[0];
    const float* end_pos  = (const float*)d_in[2];
    const float* W        = (const float*)d_in[4];
    const float* b        = (const float*)d_in[5];
    const float* gamma    = (const float*)d_in[6];
    const float* beta     = (const float*)d_in[7];
    float* X = (float*)d_out;

    __half *Ap, *Btp;
    cudaGetSymbolAddress((void**)&Ap,  g_A);
    cudaGetSymbolAddress((void**)&Btp, g_Bt);

    cudaFuncSetAttribute(gemm_kernel,
                         cudaFuncAttributeMaxDynamicSharedMemorySize, GEMM_SMEM);

    prep_kernel<<<BATCH + 1024, 64>>>(h_states, end_pos, W);

    gemm_kernel<<<dim3(NB / BNv, BATCH / BM), 256, GEMM_SMEM>>>(
        Ap, Btp, b, gamma, beta, X);
}